// round 12
// baseline (speedup 1.0000x reference)
#include <cuda_runtime.h>
#include <cuda_fp16.h>
#include <stdint.h>

// ---------------------------------------------------------------------------
// GCN2 via CSR + mma.sync TF32 tensor-core GEMM (sm_103-safe).
//   deg[d]  = 1 + indeg(d);  dinv = rsqrt(deg)   (dinv materialized in scan_c)
//   y1      = half(dinv * x)
//   aggx[d] = dinv[d] * (sum y1[s] + y1[d])       (MLP-4 gather, 8 lanes/dest)
//   h       = relu(aggx @ W1 + b1)                (TF32 mma, fp32 acc)
//   y2      = half(dinv * (h @ W2))               (TF32 mma)
//   out[d]  = dinv[d] * (sum y2[s] + y2[d]) + b2  (MLP-4 gather, 5 lanes/dest)
// Zero-state invariant: deg re-zeroed by k_scan_c (sole owner per element).
// cursor is fully overwritten by k_scan_c each call (cursor = offsets copy),
// so k_place needs no separate offsets gather and no zero invariant.
// Shapes: N=100000, F=64, H=128, C=40, E=1600000
// ---------------------------------------------------------------------------

#define NMAX 100096
#define EMAX 1600000
#define F_IN 64
#define HID  128
#define COUT 40

__device__ int    g_deg[NMAX];       // zeroed at load; re-zeroed by k_scan_c
__device__ int    g_cursor[NMAX];    // fully rewritten by k_scan_c each call
__device__ int    g_offsets[NMAX + 1];
__device__ int    g_partials[64];
__device__ int    g_sorted_src[EMAX];
__device__ float  g_dinv[NMAX];
__device__ __half g_y1[(size_t)NMAX * F_IN];
__device__ float  g_aggx[(size_t)NMAX * F_IN];
__device__ __half g_y2[(size_t)NMAX * COUT];

#define SCAN_CHUNK 2048

// ============================ small helpers ================================
__device__ __forceinline__ float tf32r(float v) {
    uint32_t o;
    asm("cvt.rna.tf32.f32 %0, %1;" : "=r"(o) : "f"(v));
    return __uint_as_float(o);
}

__device__ __forceinline__ void mma_tf32(float* c, const uint32_t* a,
                                         uint32_t b0, uint32_t b1) {
    asm volatile(
        "mma.sync.aligned.m16n8k8.row.col.f32.tf32.tf32.f32 "
        "{%0,%1,%2,%3}, {%4,%5,%6,%7}, {%8,%9}, {%0,%1,%2,%3};"
        : "+f"(c[0]), "+f"(c[1]), "+f"(c[2]), "+f"(c[3])
        : "r"(a[0]), "r"(a[1]), "r"(a[2]), "r"(a[3]), "r"(b0), "r"(b1));
}

__device__ __forceinline__ void acc8(float* acc, uint4 u) {
    float2 f;
    f = __half22float2(*(__half2*)&u.x); acc[0] += f.x; acc[1] += f.y;
    f = __half22float2(*(__half2*)&u.y); acc[2] += f.x; acc[3] += f.y;
    f = __half22float2(*(__half2*)&u.z); acc[4] += f.x; acc[5] += f.y;
    f = __half22float2(*(__half2*)&u.w); acc[6] += f.x; acc[7] += f.y;
}

// per-block index-dtype detect: int64 indices have all-zero odd words
__device__ __forceinline__ int detect_is64(const int* __restrict__ ew) {
    __shared__ int sflag;
    if (threadIdx.x == 0) {
        int all_zero = 1;
        #pragma unroll
        for (int k = 0; k < 8; k++)
            if (__ldg(ew + 2 * k + 1) != 0) all_zero = 0;
        sflag = all_zero;
    }
    __syncthreads();
    return sflag;
}

// ============================ prep kernels =================================
// hist: 2 destinations per thread via vector loads (E is even; tail-guarded)
__global__ void k_hist(const void* __restrict__ edges_raw, int* __restrict__ deg, int E) {
    int is64 = detect_is64((const int*)edges_raw);
    int e2 = blockIdx.x * blockDim.x + threadIdx.x;
    int e = e2 * 2;
    if (e >= E) return;
    int d0, d1;
    bool have1 = (e + 1 < E);
    if (is64) {
        const longlong2* p = (const longlong2*)((const long long*)edges_raw + E + e);
        longlong2 v = __ldg(p);
        d0 = (int)v.x; d1 = (int)v.y;
    } else {
        const int2* p = (const int2*)((const int*)edges_raw + E + e);
        int2 v = __ldg(p);
        d0 = v.x; d1 = v.y;
    }
    atomicAdd(&deg[d0], 1);
    if (have1) atomicAdd(&deg[d1], 1);
}

__global__ void k_scan_a(const int* __restrict__ deg, int* __restrict__ partials, int N) {
    __shared__ int sm[256];
    int b = blockIdx.x, tid = threadIdx.x;
    int base = b * SCAN_CHUNK + tid * 8;
    int s = 0;
    #pragma unroll
    for (int k = 0; k < 8; k++) {
        int i = base + k;
        if (i < N) s += deg[i];
    }
    sm[tid] = s;
    __syncthreads();
    #pragma unroll
    for (int st = 128; st > 0; st >>= 1) {
        if (tid < st) sm[tid] += sm[tid + st];
        __syncthreads();
    }
    if (tid == 0) partials[b] = sm[0];
}

// scan_c: offsets + cursor(=offsets) + dinv; restores deg[i]=0.
__global__ void k_scan_c(int* __restrict__ deg, const int* __restrict__ partials,
                         int* __restrict__ offsets, int* __restrict__ cursor,
                         float* __restrict__ dinv, int nchunks, int N) {
    __shared__ int sm[256];
    __shared__ int sbase;
    int b = blockIdx.x, tid = threadIdx.x;

    if (tid == 0) sbase = 0;
    __syncthreads();
    if (tid < 64) {
        int v = (tid < b) ? partials[tid] : 0;
        atomicAdd(&sbase, v);
    }

    int base = b * SCAN_CHUNK + tid * 8;
    int v[8];
    int s = 0;
    #pragma unroll
    for (int k = 0; k < 8; k++) {
        int i = base + k;
        v[k] = (i < N) ? deg[i] : 0;
        s += v[k];
    }
    sm[tid] = s;
    __syncthreads();
    #pragma unroll
    for (int st = 1; st < 256; st <<= 1) {
        int add = (tid >= st) ? sm[tid - st] : 0;
        __syncthreads();
        sm[tid] += add;
        __syncthreads();
    }
    int run = sm[tid] - s + sbase;
    #pragma unroll
    for (int k = 0; k < 8; k++) {
        int i = base + k;
        if (i < N) {
            offsets[i] = run;
            cursor[i]  = run;                 // place bumps this directly
            dinv[i] = rsqrtf((float)v[k] + 1.0f);
            deg[i] = 0;                       // restore zero invariant
        }
        run += v[k];
    }
    if (b == nchunks - 1 && tid == 255) offsets[N] = sm[255] + sbase;
}

// place: pos comes straight from the cursor bump (no offsets gather)
__global__ void k_place(const void* __restrict__ edges_raw,
                        int* __restrict__ cursor, int* __restrict__ sorted_src, int E) {
    int is64 = detect_is64((const int*)edges_raw);
    int e = blockIdx.x * blockDim.x + threadIdx.x;
    if (e >= E) return;
    int s, d;
    if (is64) {
        s = (int)((const long long*)edges_raw)[e];
        d = (int)((const long long*)edges_raw)[(long long)E + e];
    } else {
        s = ((const int*)edges_raw)[e];
        d = ((const int*)edges_raw)[(long long)E + e];
    }
    int pos = atomicAdd(&cursor[d], 1);
    sorted_src[pos] = s;
}

__global__ void k_y1(const float* __restrict__ x, const float* __restrict__ dinv,
                     __half* __restrict__ y1, int N) {
    int i = blockIdx.x * blockDim.x + threadIdx.x;
    if (i >= N * 16) return;
    int n = i >> 4;
    float dv = __ldg(dinv + n);
    float4 v = ((const float4*)x)[i];
    __half2 h0 = __floats2half2_rn(v.x * dv, v.y * dv);
    __half2 h1 = __floats2half2_rn(v.z * dv, v.w * dv);
    uint2 u = make_uint2(*(unsigned*)&h0, *(unsigned*)&h1);
    ((uint2*)y1)[i] = u;
}

// ===================== aggregation (round-7 layout) ========================
// agg1: 8 lanes per dest; fp16 gathers, fp32 accumulate/output, MLP-4 loop.
__global__ void k_agg1(const int* __restrict__ sorted_src, const int* __restrict__ offsets,
                       const float* __restrict__ dinv, const __half* __restrict__ y1,
                       float* __restrict__ aggx, int N) {
    int t = blockIdx.x * blockDim.x + threadIdx.x;
    int d = t >> 3, j = t & 7;
    if (d >= N) return;
    const uint4* y4 = (const uint4*)y1;
    int off = offsets[d], end = offsets[d + 1];
    float acc[8] = {0, 0, 0, 0, 0, 0, 0, 0};
    acc8(acc, y4[(size_t)d * 8 + j]);  // self term
    int i = off;
    for (; i + 4 <= end; i += 4) {
        int s0 = __ldg(sorted_src + i);
        int s1 = __ldg(sorted_src + i + 1);
        int s2 = __ldg(sorted_src + i + 2);
        int s3 = __ldg(sorted_src + i + 3);
        uint4 a = y4[(size_t)s0 * 8 + j];
        uint4 b = y4[(size_t)s1 * 8 + j];
        uint4 c = y4[(size_t)s2 * 8 + j];
        uint4 e = y4[(size_t)s3 * 8 + j];
        acc8(acc, a); acc8(acc, b); acc8(acc, c); acc8(acc, e);
    }
    if (i + 2 <= end) {
        int s0 = __ldg(sorted_src + i);
        int s1 = __ldg(sorted_src + i + 1);
        uint4 a = y4[(size_t)s0 * 8 + j];
        uint4 b = y4[(size_t)s1 * 8 + j];
        acc8(acc, a); acc8(acc, b);
        i += 2;
    }
    if (i < end) acc8(acc, y4[(size_t)__ldg(sorted_src + i) * 8 + j]);
    float dv = __ldg(dinv + d);
    float* o = aggx + (size_t)d * F_IN + j * 8;
    *(float4*)o       = make_float4(acc[0] * dv, acc[1] * dv, acc[2] * dv, acc[3] * dv);
    *(float4*)(o + 4) = make_float4(acc[4] * dv, acc[5] * dv, acc[6] * dv, acc[7] * dv);
}

// agg2: 5 lanes per dest; writes final out
__global__ void k_agg2(const int* __restrict__ sorted_src, const int* __restrict__ offsets,
                       const float* __restrict__ dinv, const __half* __restrict__ y2,
                       const float* __restrict__ b2, float* __restrict__ out, int N) {
    int t = blockIdx.x * blockDim.x + threadIdx.x;
    int d = t / 5, j = t - d * 5;
    if (d >= N) return;
    const uint4* y4 = (const uint4*)y2;
    int off = offsets[d], end = offsets[d + 1];
    float acc[8] = {0, 0, 0, 0, 0, 0, 0, 0};
    acc8(acc, y4[(size_t)d * 5 + j]);  // self term
    int i = off;
    for (; i + 4 <= end; i += 4) {
        int s0 = __ldg(sorted_src + i);
        int s1 = __ldg(sorted_src + i + 1);
        int s2 = __ldg(sorted_src + i + 2);
        int s3 = __ldg(sorted_src + i + 3);
        uint4 a = y4[(size_t)s0 * 5 + j];
        uint4 b = y4[(size_t)s1 * 5 + j];
        uint4 c = y4[(size_t)s2 * 5 + j];
        uint4 e = y4[(size_t)s3 * 5 + j];
        acc8(acc, a); acc8(acc, b); acc8(acc, c); acc8(acc, e);
    }
    if (i + 2 <= end) {
        int s0 = __ldg(sorted_src + i);
        int s1 = __ldg(sorted_src + i + 1);
        uint4 a = y4[(size_t)s0 * 5 + j];
        uint4 b = y4[(size_t)s1 * 5 + j];
        acc8(acc, a); acc8(acc, b);
        i += 2;
    }
    if (i < end) acc8(acc, y4[(size_t)__ldg(sorted_src + i) * 5 + j]);
    float dv = __ldg(dinv + d);
    const float* bb = b2 + j * 8;
    float* o = out + (size_t)d * COUT + j * 8;
    *(float4*)o       = make_float4(acc[0] * dv + bb[0], acc[1] * dv + bb[1],
                                    acc[2] * dv + bb[2], acc[3] * dv + bb[3]);
    *(float4*)(o + 4) = make_float4(acc[4] * dv + bb[4], acc[5] * dv + bb[5],
                                    acc[6] * dv + bb[6], acc[7] * dv + bb[7]);
}

// ======================= fused TF32 tensor-core GEMM =======================
#define XS_STR  68
#define BS1_STR 136
#define HS_STR  132
#define BS2_STR 72
#define GEMM_SMEM ((17408 + 9216) * 4)   // 106496 B

__global__ void __launch_bounds__(256, 2)
k_gemm(const float* __restrict__ aggx, const float* __restrict__ W1,
       const float* __restrict__ b1, const float* __restrict__ W2,
       const float* __restrict__ dinv, __half* __restrict__ y2, int N) {
    extern __shared__ float sm[];
    float* xs  = sm;            // 128 x 68
    float* bs1 = sm + 8704;     // 64 x 136
    float* hs  = sm;            // 128 x 132 (aliases xs+bs1 after sync)
    float* bs2 = sm + 17408;    // 128 x 72

    const int tid = threadIdx.x;
    const int lane = tid & 31, w = tid >> 5;
    const int g = lane >> 2, t = lane & 3;
    const int row0 = blockIdx.x * 128;

    for (int i = tid; i < 64 * 128; i += 256) {
        int k = i >> 7, n = i & 127;
        bs1[k * BS1_STR + n] = tf32r(__ldg(W1 + i));
    }
    for (int i = tid; i < 128 * 72; i += 256) {
        int k = i / 72, n = i - k * 72;
        bs2[k * BS2_STR + n] = (n < COUT) ? tf32r(__ldg(W2 + k * COUT + n)) : 0.f;
    }
    {
        const float4* A4 = (const float4*)(aggx + (size_t)row0 * F_IN);
        for (int i = tid; i < 128 * 16; i += 256) {
            float4 v = A4[i];
            float* p = xs + (i >> 4) * XS_STR + (i & 15) * 4;
            p[0] = tf32r(v.x); p[1] = tf32r(v.y);
            p[2] = tf32r(v.z); p[3] = tf32r(v.w);
        }
    }
    __syncthreads();

    const int m0 = (w & 3) * 32;
    const int n1 = (w >> 2) * 64;

    float c1[2][8][4];
    #pragma unroll
    for (int mf = 0; mf < 2; mf++)
        #pragma unroll
        for (int nf = 0; nf < 8; nf++)
            #pragma unroll
            for (int i = 0; i < 4; i++) c1[mf][nf][i] = 0.f;

    #pragma unroll
    for (int ks = 0; ks < 8; ks++) {
        int k8 = ks * 8;
        uint32_t a[2][4];
        #pragma unroll
        for (int mf = 0; mf < 2; mf++) {
            const float* p = xs + (m0 + mf * 16 + g) * XS_STR + k8 + t;
            a[mf][0] = __float_as_uint(p[0]);
            a[mf][1] = __float_as_uint(p[8 * XS_STR]);
            a[mf][2] = __float_as_uint(p[4]);
            a[mf][3] = __float_as_uint(p[8 * XS_STR + 4]);
        }
        #pragma unroll
        for (int nf = 0; nf < 8; nf++) {
            const float* bp = bs1 + (k8 + t) * BS1_STR + n1 + nf * 8 + g;
            uint32_t b0 = __float_as_uint(bp[0]);
            uint32_t b1v = __float_as_uint(bp[4 * BS1_STR]);
            mma_tf32(c1[0][nf], a[0], b0, b1v);
            mma_tf32(c1[1][nf], a[1], b0, b1v);
        }
    }
    __syncthreads();

    #pragma unroll
    for (int mf = 0; mf < 2; mf++) {
        int rb = m0 + mf * 16 + g;
        #pragma unroll
        for (int nf = 0; nf < 8; nf++) {
            int cb = n1 + nf * 8 + 2 * t;
            float bb0 = __ldg(b1 + cb), bb1 = __ldg(b1 + cb + 1);
            hs[rb * HS_STR + cb]           = tf32r(fmaxf(c1[mf][nf][0] + bb0, 0.f));
            hs[rb * HS_STR + cb + 1]       = tf32r(fmaxf(c1[mf][nf][1] + bb1, 0.f));
            hs[(rb + 8) * HS_STR + cb]     = tf32r(fmaxf(c1[mf][nf][2] + bb0, 0.f));
            hs[(rb + 8) * HS_STR + cb + 1] = tf32r(fmaxf(c1[mf][nf][3] + bb1, 0.f));
        }
    }
    __syncthreads();

    const int n2 = (w >> 2) * 32;

    float c2[2][4][4];
    #pragma unroll
    for (int mf = 0; mf < 2; mf++)
        #pragma unroll
        for (int nf = 0; nf < 4; nf++)
            #pragma unroll
            for (int i = 0; i < 4; i++) c2[mf][nf][i] = 0.f;

    #pragma unroll 4
    for (int ks = 0; ks < 16; ks++) {
        int k8 = ks * 8;
        uint32_t a[2][4];
        #pragma unroll
        for (int mf = 0; mf < 2; mf++) {
            const float* p = hs + (m0 + mf * 16 + g) * HS_STR + k8 + t;
            a[mf][0] = __float_as_uint(p[0]);
            a[mf][1] = __float_as_uint(p[8 * HS_STR]);
            a[mf][2] = __float_as_uint(p[4]);
            a[mf][3] = __float_as_uint(p[8 * HS_STR + 4]);
        }
        #pragma unroll
        for (int nf = 0; nf < 4; nf++) {
            if (n2 + nf * 8 < COUT) {
                const float* bp = bs2 + (k8 + t) * BS2_STR + n2 + nf * 8 + g;
                uint32_t b0 = __float_as_uint(bp[0]);
                uint32_t b1v = __float_as_uint(bp[4 * BS2_STR]);
                mma_tf32(c2[0][nf], a[0], b0, b1v);
                mma_tf32(c2[1][nf], a[1], b0, b1v);
            }
        }
    }

    #pragma unroll
    for (int mf = 0; mf < 2; mf++) {
        int r0g = row0 + m0 + mf * 16 + g;
        int r1g = r0g + 8;
        float dv0 = 0.f, dv1 = 0.f;
        if (r0g < N) dv0 = __ldg(dinv + r0g);
        if (r1g < N) dv1 = __ldg(dinv + r1g);
        #pragma unroll
        for (int nf = 0; nf < 4; nf++) {
            int cb = n2 + nf * 8 + 2 * t;
            if (cb < COUT) {
                if (r0g < N) {
                    __half2 h = __floats2half2_rn(c2[mf][nf][0] * dv0, c2[mf][nf][1] * dv0);
                    *(__half2*)(y2 + (size_t)r0g * COUT + cb) = h;
                }
                if (r1g < N) {
                    __half2 h = __floats2half2_rn(c2[mf][nf][2] * dv1, c2[mf][nf][3] * dv1);
                    *(__half2*)(y2 + (size_t)r1g * COUT + cb) = h;
                }
            }
        }
    }
}

// ================================ launch ===================================
extern "C" void kernel_launch(void* const* d_in, const int* in_sizes, int n_in,
                              void* d_out, int out_size) {
    const float* x     = (const float*)d_in[0];
    const void*  edges = d_in[1];
    const float* W1    = (const float*)d_in[2];
    const float* b1    = (const float*)d_in[3];
    const float* W2    = (const float*)d_in[4];
    const float* b2    = (const float*)d_in[5];
    float* out = (float*)d_out;

    const int N = in_sizes[0] / F_IN;
    const int E = in_sizes[1] / 2;
    const int nchunks = (N + SCAN_CHUNK - 1) / SCAN_CHUNK;

    int *deg, *cursor, *offsets, *partials, *ssrc;
    __half *y1, *y2;
    float *aggx, *dinv;
    cudaGetSymbolAddress((void**)&deg,      g_deg);
    cudaGetSymbolAddress((void**)&cursor,   g_cursor);
    cudaGetSymbolAddress((void**)&offsets,  g_offsets);
    cudaGetSymbolAddress((void**)&partials, g_partials);
    cudaGetSymbolAddress((void**)&ssrc,     g_sorted_src);
    cudaGetSymbolAddress((void**)&dinv,     g_dinv);
    cudaGetSymbolAddress((void**)&y1,       g_y1);
    cudaGetSymbolAddress((void**)&aggx,     g_aggx);
    cudaGetSymbolAddress((void**)&y2,       g_y2);

    cudaFuncSetAttribute(k_gemm, cudaFuncAttributeMaxDynamicSharedMemorySize, GEMM_SMEM);

    k_hist<<<(E / 2 + 255) / 256, 256>>>(edges, deg, E);                        // 0
    k_scan_a<<<nchunks, 256>>>(deg, partials, N);                               // 1
    k_scan_c<<<nchunks, 256>>>(deg, partials, offsets, cursor, dinv, nchunks, N); // 2
    k_place<<<(E + 255) / 256, 256>>>(edges, cursor, ssrc, E);                  // 3
    k_y1<<<(N * 16 + 255) / 256, 256>>>(x, dinv, y1, N);                        // 4
    k_agg1<<<(N * 8 + 255) / 256, 256>>>(ssrc, offsets, dinv, y1, aggx, N);     // 5
    k_gemm<<<(N + 127) / 128, 256, GEMM_SMEM>>>(aggx, W1, b1, W2, dinv, y2, N); // 6
    k_agg2<<<(N * 5 + 255) / 256, 256>>>(ssrc, offsets, dinv, y2, b2, out, N);  // 7
}

// round 13
// speedup vs baseline: 1.0135x; 1.0135x over previous
#include <cuda_runtime.h>
#include <cuda_fp16.h>
#include <stdint.h>

// ---------------------------------------------------------------------------
// GCN2 via CSR + mma.sync TF32 tensor-core GEMM (sm_103-safe).
//   deg[d]  = 1 + indeg(d);  dinv = rsqrt(deg)   (dinv materialized in scan_c)
//   y1      = half(dinv * x)
//   aggx[d] = dinv[d] * (sum y1[s] + y1[d])       (MLP-4 gather, 8 lanes/dest)
//   h       = relu(aggx @ W1 + b1)                (TF32 mma, fp32 acc)
//   y2      = half(dinv * (h @ W2))               (TF32 mma)
//   out[d]  = dinv[d] * (sum y2[s] + y2[d]) + b2  (MLP-4 gather, 5 lanes/dest)
// Zero-state invariant: deg re-zeroed by k_scan_c (sole owner per element).
// cursor fully rewritten by k_scan_c each call (cursor = offsets copy).
// Shapes: N=100000, F=64, H=128, C=40, E=1600000
// ---------------------------------------------------------------------------

#define NMAX 100096
#define EMAX 1600000
#define F_IN 64
#define HID  128
#define COUT 40

__device__ int    g_deg[NMAX];       // zeroed at load; re-zeroed by k_scan_c
__device__ int    g_cursor[NMAX];    // fully rewritten by k_scan_c each call
__device__ int    g_offsets[NMAX + 1];
__device__ int    g_partials[64];
__device__ int    g_sorted_src[EMAX];
__device__ float  g_dinv[NMAX];
__device__ __half g_y1[(size_t)NMAX * F_IN];
__device__ float  g_aggx[(size_t)NMAX * F_IN];
__device__ __half g_y2[(size_t)NMAX * COUT];

#define SCAN_CHUNK 2048

// ============================ small helpers ================================
__device__ __forceinline__ float tf32r(float v) {
    uint32_t o;
    asm("cvt.rna.tf32.f32 %0, %1;" : "=r"(o) : "f"(v));
    return __uint_as_float(o);
}

__device__ __forceinline__ void mma_tf32(float* c, const uint32_t* a,
                                         uint32_t b0, uint32_t b1) {
    asm volatile(
        "mma.sync.aligned.m16n8k8.row.col.f32.tf32.tf32.f32 "
        "{%0,%1,%2,%3}, {%4,%5,%6,%7}, {%8,%9}, {%0,%1,%2,%3};"
        : "+f"(c[0]), "+f"(c[1]), "+f"(c[2]), "+f"(c[3])
        : "r"(a[0]), "r"(a[1]), "r"(a[2]), "r"(a[3]), "r"(b0), "r"(b1));
}

__device__ __forceinline__ void acc8(float* acc, uint4 u) {
    float2 f;
    f = __half22float2(*(__half2*)&u.x); acc[0] += f.x; acc[1] += f.y;
    f = __half22float2(*(__half2*)&u.y); acc[2] += f.x; acc[3] += f.y;
    f = __half22float2(*(__half2*)&u.z); acc[4] += f.x; acc[5] += f.y;
    f = __half22float2(*(__half2*)&u.w); acc[6] += f.x; acc[7] += f.y;
}

// per-block index-dtype detect: int64 indices have all-zero odd words
__device__ __forceinline__ int detect_is64(const int* __restrict__ ew) {
    __shared__ int sflag;
    if (threadIdx.x == 0) {
        int all_zero = 1;
        #pragma unroll
        for (int k = 0; k < 8; k++)
            if (__ldg(ew + 2 * k + 1) != 0) all_zero = 0;
        sflag = all_zero;
    }
    __syncthreads();
    return sflag;
}

// ============================ prep kernels =================================
// hist: scalar, 1 destination per thread (round-11 measured-best form)
__global__ void k_hist(const void* __restrict__ edges_raw, int* __restrict__ deg, int E) {
    int is64 = detect_is64((const int*)edges_raw);
    int e = blockIdx.x * blockDim.x + threadIdx.x;
    if (e >= E) return;
    int d;
    if (is64) d = (int)((const long long*)edges_raw)[(long long)E + e];
    else      d = ((const int*)edges_raw)[(long long)E + e];
    atomicAdd(&deg[d], 1);
}

__global__ void k_scan_a(const int* __restrict__ deg, int* __restrict__ partials, int N) {
    __shared__ int sm[256];
    int b = blockIdx.x, tid = threadIdx.x;
    int base = b * SCAN_CHUNK + tid * 8;
    int s = 0;
    #pragma unroll
    for (int k = 0; k < 8; k++) {
        int i = base + k;
        if (i < N) s += deg[i];
    }
    sm[tid] = s;
    __syncthreads();
    #pragma unroll
    for (int st = 128; st > 0; st >>= 1) {
        if (tid < st) sm[tid] += sm[tid + st];
        __syncthreads();
    }
    if (tid == 0) partials[b] = sm[0];
}

// scan_c: offsets + cursor(=offsets) + dinv; restores deg[i]=0.
__global__ void k_scan_c(int* __restrict__ deg, const int* __restrict__ partials,
                         int* __restrict__ offsets, int* __restrict__ cursor,
                         float* __restrict__ dinv, int nchunks, int N) {
    __shared__ int sm[256];
    __shared__ int sbase;
    int b = blockIdx.x, tid = threadIdx.x;

    if (tid == 0) sbase = 0;
    __syncthreads();
    if (tid < 64) {
        int v = (tid < b) ? partials[tid] : 0;
        atomicAdd(&sbase, v);
    }

    int base = b * SCAN_CHUNK + tid * 8;
    int v[8];
    int s = 0;
    #pragma unroll
    for (int k = 0; k < 8; k++) {
        int i = base + k;
        v[k] = (i < N) ? deg[i] : 0;
        s += v[k];
    }
    sm[tid] = s;
    __syncthreads();
    #pragma unroll
    for (int st = 1; st < 256; st <<= 1) {
        int add = (tid >= st) ? sm[tid - st] : 0;
        __syncthreads();
        sm[tid] += add;
        __syncthreads();
    }
    int run = sm[tid] - s + sbase;
    #pragma unroll
    for (int k = 0; k < 8; k++) {
        int i = base + k;
        if (i < N) {
            offsets[i] = run;
            cursor[i]  = run;                 // place bumps this directly
            dinv[i] = rsqrtf((float)v[k] + 1.0f);
            deg[i] = 0;                       // restore zero invariant
        }
        run += v[k];
    }
    if (b == nchunks - 1 && tid == 255) offsets[N] = sm[255] + sbase;
}

// place: 2 edges per thread, vectorized coalesced index loads, two
// independent atomic chains per thread (MLP 2). E is even for this dataset;
// odd tail handled by the last thread's guard.
__global__ void k_place(const void* __restrict__ edges_raw,
                        int* __restrict__ cursor, int* __restrict__ sorted_src, int E) {
    int is64 = detect_is64((const int*)edges_raw);
    int e = (blockIdx.x * blockDim.x + threadIdx.x) * 2;
    if (e >= E) return;
    int s0, d0, s1 = 0, d1 = 0;
    bool have1 = (e + 1 < E);
    if (is64) {
        longlong2 vs = __ldg((const longlong2*)((const long long*)edges_raw + e));
        longlong2 vd = __ldg((const longlong2*)((const long long*)edges_raw + E + e));
        s0 = (int)vs.x; s1 = (int)vs.y;
        d0 = (int)vd.x; d1 = (int)vd.y;
    } else {
        int2 vs = __ldg((const int2*)((const int*)edges_raw + e));
        int2 vd = __ldg((const int2*)((const int*)edges_raw + E + e));
        s0 = vs.x; s1 = vs.y;
        d0 = vd.x; d1 = vd.y;
    }
    int p0 = atomicAdd(&cursor[d0], 1);
    int p1 = have1 ? atomicAdd(&cursor[d1], 1) : 0;
    sorted_src[p0] = s0;
    if (have1) sorted_src[p1] = s1;
}

__global__ void k_y1(const float* __restrict__ x, const float* __restrict__ dinv,
                     __half* __restrict__ y1, int N) {
    int i = blockIdx.x * blockDim.x + threadIdx.x;
    if (i >= N * 16) return;
    int n = i >> 4;
    float dv = __ldg(dinv + n);
    float4 v = ((const float4*)x)[i];
    __half2 h0 = __floats2half2_rn(v.x * dv, v.y * dv);
    __half2 h1 = __floats2half2_rn(v.z * dv, v.w * dv);
    uint2 u = make_uint2(*(unsigned*)&h0, *(unsigned*)&h1);
    ((uint2*)y1)[i] = u;
}

// ===================== aggregation (round-7 layout) ========================
// agg1: 8 lanes per dest; fp16 gathers, fp32 accumulate/output, MLP-4 loop.
__global__ void k_agg1(const int* __restrict__ sorted_src, const int* __restrict__ offsets,
                       const float* __restrict__ dinv, const __half* __restrict__ y1,
                       float* __restrict__ aggx, int N) {
    int t = blockIdx.x * blockDim.x + threadIdx.x;
    int d = t >> 3, j = t & 7;
    if (d >= N) return;
    const uint4* y4 = (const uint4*)y1;
    int off = offsets[d], end = offsets[d + 1];
    float acc[8] = {0, 0, 0, 0, 0, 0, 0, 0};
    acc8(acc, y4[(size_t)d * 8 + j]);  // self term
    int i = off;
    for (; i + 4 <= end; i += 4) {
        int s0 = __ldg(sorted_src + i);
        int s1 = __ldg(sorted_src + i + 1);
        int s2 = __ldg(sorted_src + i + 2);
        int s3 = __ldg(sorted_src + i + 3);
        uint4 a = y4[(size_t)s0 * 8 + j];
        uint4 b = y4[(size_t)s1 * 8 + j];
        uint4 c = y4[(size_t)s2 * 8 + j];
        uint4 e = y4[(size_t)s3 * 8 + j];
        acc8(acc, a); acc8(acc, b); acc8(acc, c); acc8(acc, e);
    }
    if (i + 2 <= end) {
        int s0 = __ldg(sorted_src + i);
        int s1 = __ldg(sorted_src + i + 1);
        uint4 a = y4[(size_t)s0 * 8 + j];
        uint4 b = y4[(size_t)s1 * 8 + j];
        acc8(acc, a); acc8(acc, b);
        i += 2;
    }
    if (i < end) acc8(acc, y4[(size_t)__ldg(sorted_src + i) * 8 + j]);
    float dv = __ldg(dinv + d);
    float* o = aggx + (size_t)d * F_IN + j * 8;
    *(float4*)o       = make_float4(acc[0] * dv, acc[1] * dv, acc[2] * dv, acc[3] * dv);
    *(float4*)(o + 4) = make_float4(acc[4] * dv, acc[5] * dv, acc[6] * dv, acc[7] * dv);
}

// agg2: 5 lanes per dest; writes final out
__global__ void k_agg2(const int* __restrict__ sorted_src, const int* __restrict__ offsets,
                       const float* __restrict__ dinv, const __half* __restrict__ y2,
                       const float* __restrict__ b2, float* __restrict__ out, int N) {
    int t = blockIdx.x * blockDim.x + threadIdx.x;
    int d = t / 5, j = t - d * 5;
    if (d >= N) return;
    const uint4* y4 = (const uint4*)y2;
    int off = offsets[d], end = offsets[d + 1];
    float acc[8] = {0, 0, 0, 0, 0, 0, 0, 0};
    acc8(acc, y4[(size_t)d * 5 + j]);  // self term
    int i = off;
    for (; i + 4 <= end; i += 4) {
        int s0 = __ldg(sorted_src + i);
        int s1 = __ldg(sorted_src + i + 1);
        int s2 = __ldg(sorted_src + i + 2);
        int s3 = __ldg(sorted_src + i + 3);
        uint4 a = y4[(size_t)s0 * 5 + j];
        uint4 b = y4[(size_t)s1 * 5 + j];
        uint4 c = y4[(size_t)s2 * 5 + j];
        uint4 e = y4[(size_t)s3 * 5 + j];
        acc8(acc, a); acc8(acc, b); acc8(acc, c); acc8(acc, e);
    }
    if (i + 2 <= end) {
        int s0 = __ldg(sorted_src + i);
        int s1 = __ldg(sorted_src + i + 1);
        uint4 a = y4[(size_t)s0 * 5 + j];
        uint4 b = y4[(size_t)s1 * 5 + j];
        acc8(acc, a); acc8(acc, b);
        i += 2;
    }
    if (i < end) acc8(acc, y4[(size_t)__ldg(sorted_src + i) * 5 + j]);
    float dv = __ldg(dinv + d);
    const float* bb = b2 + j * 8;
    float* o = out + (size_t)d * COUT + j * 8;
    *(float4*)o       = make_float4(acc[0] * dv + bb[0], acc[1] * dv + bb[1],
                                    acc[2] * dv + bb[2], acc[3] * dv + bb[3]);
    *(float4*)(o + 4) = make_float4(acc[4] * dv + bb[4], acc[5] * dv + bb[5],
                                    acc[6] * dv + bb[6], acc[7] * dv + bb[7]);
}

// ======================= fused TF32 tensor-core GEMM =======================
#define XS_STR  68
#define BS1_STR 136
#define HS_STR  132
#define BS2_STR 72
#define GEMM_SMEM ((17408 + 9216) * 4)   // 106496 B

__global__ void __launch_bounds__(256, 2)
k_gemm(const float* __restrict__ aggx, const float* __restrict__ W1,
       const float* __restrict__ b1, const float* __restrict__ W2,
       const float* __restrict__ dinv, __half* __restrict__ y2, int N) {
    extern __shared__ float sm[];
    float* xs  = sm;            // 128 x 68
    float* bs1 = sm + 8704;     // 64 x 136
    float* hs  = sm;            // 128 x 132 (aliases xs+bs1 after sync)
    float* bs2 = sm + 17408;    // 128 x 72

    const int tid = threadIdx.x;
    const int lane = tid & 31, w = tid >> 5;
    const int g = lane >> 2, t = lane & 3;
    const int row0 = blockIdx.x * 128;

    for (int i = tid; i < 64 * 128; i += 256) {
        int k = i >> 7, n = i & 127;
        bs1[k * BS1_STR + n] = tf32r(__ldg(W1 + i));
    }
    for (int i = tid; i < 128 * 72; i += 256) {
        int k = i / 72, n = i - k * 72;
        bs2[k * BS2_STR + n] = (n < COUT) ? tf32r(__ldg(W2 + k * COUT + n)) : 0.f;
    }
    {
        const float4* A4 = (const float4*)(aggx + (size_t)row0 * F_IN);
        for (int i = tid; i < 128 * 16; i += 256) {
            float4 v = A4[i];
            float* p = xs + (i >> 4) * XS_STR + (i & 15) * 4;
            p[0] = tf32r(v.x); p[1] = tf32r(v.y);
            p[2] = tf32r(v.z); p[3] = tf32r(v.w);
        }
    }
    __syncthreads();

    const int m0 = (w & 3) * 32;
    const int n1 = (w >> 2) * 64;

    float c1[2][8][4];
    #pragma unroll
    for (int mf = 0; mf < 2; mf++)
        #pragma unroll
        for (int nf = 0; nf < 8; nf++)
            #pragma unroll
            for (int i = 0; i < 4; i++) c1[mf][nf][i] = 0.f;

    #pragma unroll
    for (int ks = 0; ks < 8; ks++) {
        int k8 = ks * 8;
        uint32_t a[2][4];
        #pragma unroll
        for (int mf = 0; mf < 2; mf++) {
            const float* p = xs + (m0 + mf * 16 + g) * XS_STR + k8 + t;
            a[mf][0] = __float_as_uint(p[0]);
            a[mf][1] = __float_as_uint(p[8 * XS_STR]);
            a[mf][2] = __float_as_uint(p[4]);
            a[mf][3] = __float_as_uint(p[8 * XS_STR + 4]);
        }
        #pragma unroll
        for (int nf = 0; nf < 8; nf++) {
            const float* bp = bs1 + (k8 + t) * BS1_STR + n1 + nf * 8 + g;
            uint32_t b0 = __float_as_uint(bp[0]);
            uint32_t b1v = __float_as_uint(bp[4 * BS1_STR]);
            mma_tf32(c1[0][nf], a[0], b0, b1v);
            mma_tf32(c1[1][nf], a[1], b0, b1v);
        }
    }
    __syncthreads();

    #pragma unroll
    for (int mf = 0; mf < 2; mf++) {
        int rb = m0 + mf * 16 + g;
        #pragma unroll
        for (int nf = 0; nf < 8; nf++) {
            int cb = n1 + nf * 8 + 2 * t;
            float bb0 = __ldg(b1 + cb), bb1 = __ldg(b1 + cb + 1);
            hs[rb * HS_STR + cb]           = tf32r(fmaxf(c1[mf][nf][0] + bb0, 0.f));
            hs[rb * HS_STR + cb + 1]       = tf32r(fmaxf(c1[mf][nf][1] + bb1, 0.f));
            hs[(rb + 8) * HS_STR + cb]     = tf32r(fmaxf(c1[mf][nf][2] + bb0, 0.f));
            hs[(rb + 8) * HS_STR + cb + 1] = tf32r(fmaxf(c1[mf][nf][3] + bb1, 0.f));
        }
    }
    __syncthreads();

    const int n2 = (w >> 2) * 32;

    float c2[2][4][4];
    #pragma unroll
    for (int mf = 0; mf < 2; mf++)
        #pragma unroll
        for (int nf = 0; nf < 4; nf++)
            #pragma unroll
            for (int i = 0; i < 4; i++) c2[mf][nf][i] = 0.f;

    #pragma unroll 4
    for (int ks = 0; ks < 16; ks++) {
        int k8 = ks * 8;
        uint32_t a[2][4];
        #pragma unroll
        for (int mf = 0; mf < 2; mf++) {
            const float* p = hs + (m0 + mf * 16 + g) * HS_STR + k8 + t;
            a[mf][0] = __float_as_uint(p[0]);
            a[mf][1] = __float_as_uint(p[8 * HS_STR]);
            a[mf][2] = __float_as_uint(p[4]);
            a[mf][3] = __float_as_uint(p[8 * HS_STR + 4]);
        }
        #pragma unroll
        for (int nf = 0; nf < 4; nf++) {
            if (n2 + nf * 8 < COUT) {
                const float* bp = bs2 + (k8 + t) * BS2_STR + n2 + nf * 8 + g;
                uint32_t b0 = __float_as_uint(bp[0]);
                uint32_t b1v = __float_as_uint(bp[4 * BS2_STR]);
                mma_tf32(c2[0][nf], a[0], b0, b1v);
                mma_tf32(c2[1][nf], a[1], b0, b1v);
            }
        }
    }

    #pragma unroll
    for (int mf = 0; mf < 2; mf++) {
        int r0g = row0 + m0 + mf * 16 + g;
        int r1g = r0g + 8;
        float dv0 = 0.f, dv1 = 0.f;
        if (r0g < N) dv0 = __ldg(dinv + r0g);
        if (r1g < N) dv1 = __ldg(dinv + r1g);
        #pragma unroll
        for (int nf = 0; nf < 4; nf++) {
            int cb = n2 + nf * 8 + 2 * t;
            if (cb < COUT) {
                if (r0g < N) {
                    __half2 h = __floats2half2_rn(c2[mf][nf][0] * dv0, c2[mf][nf][1] * dv0);
                    *(__half2*)(y2 + (size_t)r0g * COUT + cb) = h;
                }
                if (r1g < N) {
                    __half2 h = __floats2half2_rn(c2[mf][nf][2] * dv1, c2[mf][nf][3] * dv1);
                    *(__half2*)(y2 + (size_t)r1g * COUT + cb) = h;
                }
            }
        }
    }
}

// ================================ launch ===================================
extern "C" void kernel_launch(void* const* d_in, const int* in_sizes, int n_in,
                              void* d_out, int out_size) {
    const float* x     = (const float*)d_in[0];
    const void*  edges = d_in[1];
    const float* W1    = (const float*)d_in[2];
    const float* b1    = (const float*)d_in[3];
    const float* W2    = (const float*)d_in[4];
    const float* b2    = (const float*)d_in[5];
    float* out = (float*)d_out;

    const int N = in_sizes[0] / F_IN;
    const int E = in_sizes[1] / 2;
    const int nchunks = (N + SCAN_CHUNK - 1) / SCAN_CHUNK;

    int *deg, *cursor, *offsets, *partials, *ssrc;
    __half *y1, *y2;
    float *aggx, *dinv;
    cudaGetSymbolAddress((void**)&deg,      g_deg);
    cudaGetSymbolAddress((void**)&cursor,   g_cursor);
    cudaGetSymbolAddress((void**)&offsets,  g_offsets);
    cudaGetSymbolAddress((void**)&partials, g_partials);
    cudaGetSymbolAddress((void**)&ssrc,     g_sorted_src);
    cudaGetSymbolAddress((void**)&dinv,     g_dinv);
    cudaGetSymbolAddress((void**)&y1,       g_y1);
    cudaGetSymbolAddress((void**)&aggx,     g_aggx);
    cudaGetSymbolAddress((void**)&y2,       g_y2);

    cudaFuncSetAttribute(k_gemm, cudaFuncAttributeMaxDynamicSharedMemorySize, GEMM_SMEM);

    k_hist<<<(E + 255) / 256, 256>>>(edges, deg, E);                            // 0
    k_scan_a<<<nchunks, 256>>>(deg, partials, N);                               // 1
    k_scan_c<<<nchunks, 256>>>(deg, partials, offsets, cursor, dinv, nchunks, N); // 2
    k_place<<<(E / 2 + 255) / 256, 256>>>(edges, cursor, ssrc, E);              // 3
    k_y1<<<(N * 16 + 255) / 256, 256>>>(x, dinv, y1, N);                        // 4
    k_agg1<<<(N * 8 + 255) / 256, 256>>>(ssrc, offsets, dinv, y1, aggx, N);     // 5
    k_gemm<<<(N + 127) / 128, 256, GEMM_SMEM>>>(aggx, W1, b1, W2, dinv, y2, N); // 6
    k_agg2<<<(N * 5 + 255) / 256, 256>>>(ssrc, offsets, dinv, y2, b2, out, N);  // 7
}

// round 14
// speedup vs baseline: 1.0269x; 1.0132x over previous
#include <cuda_runtime.h>
#include <cuda_fp16.h>
#include <stdint.h>

// ---------------------------------------------------------------------------
// GCN2 via CSR + mma.sync TF32 tensor-core GEMM (sm_103-safe).
//   deg[d]  = 1 + indeg(d);  dinv = rsqrt(deg)   (dinv materialized in scan_c)
//   y1      = half(dinv * x)
//   aggx[d] = dinv[d] * (sum y1[s] + y1[d])       (MLP-4 gather, 8 lanes/dest)
//   h       = relu(aggx @ W1 + b1)                (TF32 mma, fp32 acc)
//   y2      = half(dinv * (h @ W2))               (TF32 mma)
//   out[d]  = dinv[d] * (sum y2[s] + y2[d]) + b2  (MLP-4 gather, 5 lanes/dest)
// Graph shape: scan_c forks into {place (main stream), y1 (side stream)};
// join before agg1. place is atomic-bound, y1 is DRAM-bound -> overlap.
// Zero-state invariant: deg re-zeroed by k_scan_c; cursor fully rewritten.
// ---------------------------------------------------------------------------

#define NMAX 100096
#define EMAX 1600000
#define F_IN 64
#define HID  128
#define COUT 40

__device__ int    g_deg[NMAX];
__device__ int    g_cursor[NMAX];
__device__ int    g_offsets[NMAX + 1];
__device__ int    g_partials[64];
__device__ int    g_sorted_src[EMAX];
__device__ float  g_dinv[NMAX];
__device__ __half g_y1[(size_t)NMAX * F_IN];
__device__ float  g_aggx[(size_t)NMAX * F_IN];
__device__ __half g_y2[(size_t)NMAX * COUT];

#define SCAN_CHUNK 2048

// ============================ small helpers ================================
__device__ __forceinline__ float tf32r(float v) {
    uint32_t o;
    asm("cvt.rna.tf32.f32 %0, %1;" : "=r"(o) : "f"(v));
    return __uint_as_float(o);
}

__device__ __forceinline__ void mma_tf32(float* c, const uint32_t* a,
                                         uint32_t b0, uint32_t b1) {
    asm volatile(
        "mma.sync.aligned.m16n8k8.row.col.f32.tf32.tf32.f32 "
        "{%0,%1,%2,%3}, {%4,%5,%6,%7}, {%8,%9}, {%0,%1,%2,%3};"
        : "+f"(c[0]), "+f"(c[1]), "+f"(c[2]), "+f"(c[3])
        : "r"(a[0]), "r"(a[1]), "r"(a[2]), "r"(a[3]), "r"(b0), "r"(b1));
}

__device__ __forceinline__ void acc8(float* acc, uint4 u) {
    float2 f;
    f = __half22float2(*(__half2*)&u.x); acc[0] += f.x; acc[1] += f.y;
    f = __half22float2(*(__half2*)&u.y); acc[2] += f.x; acc[3] += f.y;
    f = __half22float2(*(__half2*)&u.z); acc[4] += f.x; acc[5] += f.y;
    f = __half22float2(*(__half2*)&u.w); acc[6] += f.x; acc[7] += f.y;
}

__device__ __forceinline__ int detect_is64(const int* __restrict__ ew) {
    __shared__ int sflag;
    if (threadIdx.x == 0) {
        int all_zero = 1;
        #pragma unroll
        for (int k = 0; k < 8; k++)
            if (__ldg(ew + 2 * k + 1) != 0) all_zero = 0;
        sflag = all_zero;
    }
    __syncthreads();
    return sflag;
}

// ============================ prep kernels =================================
__global__ void k_hist(const void* __restrict__ edges_raw, int* __restrict__ deg, int E) {
    int is64 = detect_is64((const int*)edges_raw);
    int e = blockIdx.x * blockDim.x + threadIdx.x;
    if (e >= E) return;
    int d;
    if (is64) d = (int)((const long long*)edges_raw)[(long long)E + e];
    else      d = ((const int*)edges_raw)[(long long)E + e];
    atomicAdd(&deg[d], 1);
}

__global__ void k_scan_a(const int* __restrict__ deg, int* __restrict__ partials, int N) {
    __shared__ int sm[256];
    int b = blockIdx.x, tid = threadIdx.x;
    int base = b * SCAN_CHUNK + tid * 8;
    int s = 0;
    #pragma unroll
    for (int k = 0; k < 8; k++) {
        int i = base + k;
        if (i < N) s += deg[i];
    }
    sm[tid] = s;
    __syncthreads();
    #pragma unroll
    for (int st = 128; st > 0; st >>= 1) {
        if (tid < st) sm[tid] += sm[tid + st];
        __syncthreads();
    }
    if (tid == 0) partials[b] = sm[0];
}

__global__ void k_scan_c(int* __restrict__ deg, const int* __restrict__ partials,
                         int* __restrict__ offsets, int* __restrict__ cursor,
                         float* __restrict__ dinv, int nchunks, int N) {
    __shared__ int sm[256];
    __shared__ int sbase;
    int b = blockIdx.x, tid = threadIdx.x;

    if (tid == 0) sbase = 0;
    __syncthreads();
    if (tid < 64) {
        int v = (tid < b) ? partials[tid] : 0;
        atomicAdd(&sbase, v);
    }

    int base = b * SCAN_CHUNK + tid * 8;
    int v[8];
    int s = 0;
    #pragma unroll
    for (int k = 0; k < 8; k++) {
        int i = base + k;
        v[k] = (i < N) ? deg[i] : 0;
        s += v[k];
    }
    sm[tid] = s;
    __syncthreads();
    #pragma unroll
    for (int st = 1; st < 256; st <<= 1) {
        int add = (tid >= st) ? sm[tid - st] : 0;
        __syncthreads();
        sm[tid] += add;
        __syncthreads();
    }
    int run = sm[tid] - s + sbase;
    #pragma unroll
    for (int k = 0; k < 8; k++) {
        int i = base + k;
        if (i < N) {
            offsets[i] = run;
            cursor[i]  = run;
            dinv[i] = rsqrtf((float)v[k] + 1.0f);
            deg[i] = 0;
        }
        run += v[k];
    }
    if (b == nchunks - 1 && tid == 255) offsets[N] = sm[255] + sbase;
}

// place: 1 edge per thread, cursor-direct (measured best: 23.7us)
__global__ void k_place(const void* __restrict__ edges_raw,
                        int* __restrict__ cursor, int* __restrict__ sorted_src, int E) {
    int is64 = detect_is64((const int*)edges_raw);
    int e = blockIdx.x * blockDim.x + threadIdx.x;
    if (e >= E) return;
    int s, d;
    if (is64) {
        s = (int)((const long long*)edges_raw)[e];
        d = (int)((const long long*)edges_raw)[(long long)E + e];
    } else {
        s = ((const int*)edges_raw)[e];
        d = ((const int*)edges_raw)[(long long)E + e];
    }
    int pos = atomicAdd(&cursor[d], 1);
    sorted_src[pos] = s;
}

__global__ void k_y1(const float* __restrict__ x, const float* __restrict__ dinv,
                     __half* __restrict__ y1, int N) {
    int i = blockIdx.x * blockDim.x + threadIdx.x;
    if (i >= N * 16) return;
    int n = i >> 4;
    float dv = __ldg(dinv + n);
    float4 v = ((const float4*)x)[i];
    __half2 h0 = __floats2half2_rn(v.x * dv, v.y * dv);
    __half2 h1 = __floats2half2_rn(v.z * dv, v.w * dv);
    uint2 u = make_uint2(*(unsigned*)&h0, *(unsigned*)&h1);
    ((uint2*)y1)[i] = u;
}

// ===================== aggregation (round-7 layout) ========================
__global__ void k_agg1(const int* __restrict__ sorted_src, const int* __restrict__ offsets,
                       const float* __restrict__ dinv, const __half* __restrict__ y1,
                       float* __restrict__ aggx, int N) {
    int t = blockIdx.x * blockDim.x + threadIdx.x;
    int d = t >> 3, j = t & 7;
    if (d >= N) return;
    const uint4* y4 = (const uint4*)y1;
    int off = offsets[d], end = offsets[d + 1];
    float acc[8] = {0, 0, 0, 0, 0, 0, 0, 0};
    acc8(acc, y4[(size_t)d * 8 + j]);
    int i = off;
    for (; i + 4 <= end; i += 4) {
        int s0 = __ldg(sorted_src + i);
        int s1 = __ldg(sorted_src + i + 1);
        int s2 = __ldg(sorted_src + i + 2);
        int s3 = __ldg(sorted_src + i + 3);
        uint4 a = y4[(size_t)s0 * 8 + j];
        uint4 b = y4[(size_t)s1 * 8 + j];
        uint4 c = y4[(size_t)s2 * 8 + j];
        uint4 e = y4[(size_t)s3 * 8 + j];
        acc8(acc, a); acc8(acc, b); acc8(acc, c); acc8(acc, e);
    }
    if (i + 2 <= end) {
        int s0 = __ldg(sorted_src + i);
        int s1 = __ldg(sorted_src + i + 1);
        uint4 a = y4[(size_t)s0 * 8 + j];
        uint4 b = y4[(size_t)s1 * 8 + j];
        acc8(acc, a); acc8(acc, b);
        i += 2;
    }
    if (i < end) acc8(acc, y4[(size_t)__ldg(sorted_src + i) * 8 + j]);
    float dv = __ldg(dinv + d);
    float* o = aggx + (size_t)d * F_IN + j * 8;
    *(float4*)o       = make_float4(acc[0] * dv, acc[1] * dv, acc[2] * dv, acc[3] * dv);
    *(float4*)(o + 4) = make_float4(acc[4] * dv, acc[5] * dv, acc[6] * dv, acc[7] * dv);
}

__global__ void k_agg2(const int* __restrict__ sorted_src, const int* __restrict__ offsets,
                       const float* __restrict__ dinv, const __half* __restrict__ y2,
                       const float* __restrict__ b2, float* __restrict__ out, int N) {
    int t = blockIdx.x * blockDim.x + threadIdx.x;
    int d = t / 5, j = t - d * 5;
    if (d >= N) return;
    const uint4* y4 = (const uint4*)y2;
    int off = offsets[d], end = offsets[d + 1];
    float acc[8] = {0, 0, 0, 0, 0, 0, 0, 0};
    acc8(acc, y4[(size_t)d * 5 + j]);
    int i = off;
    for (; i + 4 <= end; i += 4) {
        int s0 = __ldg(sorted_src + i);
        int s1 = __ldg(sorted_src + i + 1);
        int s2 = __ldg(sorted_src + i + 2);
        int s3 = __ldg(sorted_src + i + 3);
        uint4 a = y4[(size_t)s0 * 5 + j];
        uint4 b = y4[(size_t)s1 * 5 + j];
        uint4 c = y4[(size_t)s2 * 5 + j];
        uint4 e = y4[(size_t)s3 * 5 + j];
        acc8(acc, a); acc8(acc, b); acc8(acc, c); acc8(acc, e);
    }
    if (i + 2 <= end) {
        int s0 = __ldg(sorted_src + i);
        int s1 = __ldg(sorted_src + i + 1);
        uint4 a = y4[(size_t)s0 * 5 + j];
        uint4 b = y4[(size_t)s1 * 5 + j];
        acc8(acc, a); acc8(acc, b);
        i += 2;
    }
    if (i < end) acc8(acc, y4[(size_t)__ldg(sorted_src + i) * 5 + j]);
    float dv = __ldg(dinv + d);
    const float* bb = b2 + j * 8;
    float* o = out + (size_t)d * COUT + j * 8;
    *(float4*)o       = make_float4(acc[0] * dv + bb[0], acc[1] * dv + bb[1],
                                    acc[2] * dv + bb[2], acc[3] * dv + bb[3]);
    *(float4*)(o + 4) = make_float4(acc[4] * dv + bb[4], acc[5] * dv + bb[5],
                                    acc[6] * dv + bb[6], acc[7] * dv + bb[7]);
}

// ======================= fused TF32 tensor-core GEMM =======================
#define XS_STR  68
#define BS1_STR 136
#define HS_STR  132
#define BS2_STR 72
#define GEMM_SMEM ((17408 + 9216) * 4)   // 106496 B

__global__ void __launch_bounds__(256, 2)
k_gemm(const float* __restrict__ aggx, const float* __restrict__ W1,
       const float* __restrict__ b1, const float* __restrict__ W2,
       const float* __restrict__ dinv, __half* __restrict__ y2, int N) {
    extern __shared__ float sm[];
    float* xs  = sm;            // 128 x 68
    float* bs1 = sm + 8704;     // 64 x 136
    float* hs  = sm;            // 128 x 132 (aliases xs+bs1 after sync)
    float* bs2 = sm + 17408;    // 128 x 72

    const int tid = threadIdx.x;
    const int lane = tid & 31, w = tid >> 5;
    const int g = lane >> 2, t = lane & 3;
    const int row0 = blockIdx.x * 128;

    for (int i = tid; i < 64 * 128; i += 256) {
        int k = i >> 7, n = i & 127;
        bs1[k * BS1_STR + n] = tf32r(__ldg(W1 + i));
    }
    for (int i = tid; i < 128 * 72; i += 256) {
        int k = i / 72, n = i - k * 72;
        bs2[k * BS2_STR + n] = (n < COUT) ? tf32r(__ldg(W2 + k * COUT + n)) : 0.f;
    }
    {
        const float4* A4 = (const float4*)(aggx + (size_t)row0 * F_IN);
        for (int i = tid; i < 128 * 16; i += 256) {
            float4 v = A4[i];
            float* p = xs + (i >> 4) * XS_STR + (i & 15) * 4;
            p[0] = tf32r(v.x); p[1] = tf32r(v.y);
            p[2] = tf32r(v.z); p[3] = tf32r(v.w);
        }
    }
    __syncthreads();

    const int m0 = (w & 3) * 32;
    const int n1 = (w >> 2) * 64;

    float c1[2][8][4];
    #pragma unroll
    for (int mf = 0; mf < 2; mf++)
        #pragma unroll
        for (int nf = 0; nf < 8; nf++)
            #pragma unroll
            for (int i = 0; i < 4; i++) c1[mf][nf][i] = 0.f;

    #pragma unroll
    for (int ks = 0; ks < 8; ks++) {
        int k8 = ks * 8;
        uint32_t a[2][4];
        #pragma unroll
        for (int mf = 0; mf < 2; mf++) {
            const float* p = xs + (m0 + mf * 16 + g) * XS_STR + k8 + t;
            a[mf][0] = __float_as_uint(p[0]);
            a[mf][1] = __float_as_uint(p[8 * XS_STR]);
            a[mf][2] = __float_as_uint(p[4]);
            a[mf][3] = __float_as_uint(p[8 * XS_STR + 4]);
        }
        #pragma unroll
        for (int nf = 0; nf < 8; nf++) {
            const float* bp = bs1 + (k8 + t) * BS1_STR + n1 + nf * 8 + g;
            uint32_t b0 = __float_as_uint(bp[0]);
            uint32_t b1v = __float_as_uint(bp[4 * BS1_STR]);
            mma_tf32(c1[0][nf], a[0], b0, b1v);
            mma_tf32(c1[1][nf], a[1], b0, b1v);
        }
    }
    __syncthreads();

    #pragma unroll
    for (int mf = 0; mf < 2; mf++) {
        int rb = m0 + mf * 16 + g;
        #pragma unroll
        for (int nf = 0; nf < 8; nf++) {
            int cb = n1 + nf * 8 + 2 * t;
            float bb0 = __ldg(b1 + cb), bb1 = __ldg(b1 + cb + 1);
            hs[rb * HS_STR + cb]           = tf32r(fmaxf(c1[mf][nf][0] + bb0, 0.f));
            hs[rb * HS_STR + cb + 1]       = tf32r(fmaxf(c1[mf][nf][1] + bb1, 0.f));
            hs[(rb + 8) * HS_STR + cb]     = tf32r(fmaxf(c1[mf][nf][2] + bb0, 0.f));
            hs[(rb + 8) * HS_STR + cb + 1] = tf32r(fmaxf(c1[mf][nf][3] + bb1, 0.f));
        }
    }
    __syncthreads();

    const int n2 = (w >> 2) * 32;

    float c2[2][4][4];
    #pragma unroll
    for (int mf = 0; mf < 2; mf++)
        #pragma unroll
        for (int nf = 0; nf < 4; nf++)
            #pragma unroll
            for (int i = 0; i < 4; i++) c2[mf][nf][i] = 0.f;

    #pragma unroll 4
    for (int ks = 0; ks < 16; ks++) {
        int k8 = ks * 8;
        uint32_t a[2][4];
        #pragma unroll
        for (int mf = 0; mf < 2; mf++) {
            const float* p = hs + (m0 + mf * 16 + g) * HS_STR + k8 + t;
            a[mf][0] = __float_as_uint(p[0]);
            a[mf][1] = __float_as_uint(p[8 * HS_STR]);
            a[mf][2] = __float_as_uint(p[4]);
            a[mf][3] = __float_as_uint(p[8 * HS_STR + 4]);
        }
        #pragma unroll
        for (int nf = 0; nf < 4; nf++) {
            if (n2 + nf * 8 < COUT) {
                const float* bp = bs2 + (k8 + t) * BS2_STR + n2 + nf * 8 + g;
                uint32_t b0 = __float_as_uint(bp[0]);
                uint32_t b1v = __float_as_uint(bp[4 * BS2_STR]);
                mma_tf32(c2[0][nf], a[0], b0, b1v);
                mma_tf32(c2[1][nf], a[1], b0, b1v);
            }
        }
    }

    #pragma unroll
    for (int mf = 0; mf < 2; mf++) {
        int r0g = row0 + m0 + mf * 16 + g;
        int r1g = r0g + 8;
        float dv0 = 0.f, dv1 = 0.f;
        if (r0g < N) dv0 = __ldg(dinv + r0g);
        if (r1g < N) dv1 = __ldg(dinv + r1g);
        #pragma unroll
        for (int nf = 0; nf < 4; nf++) {
            int cb = n2 + nf * 8 + 2 * t;
            if (cb < COUT) {
                if (r0g < N) {
                    __half2 h = __floats2half2_rn(c2[mf][nf][0] * dv0, c2[mf][nf][1] * dv0);
                    *(__half2*)(y2 + (size_t)r0g * COUT + cb) = h;
                }
                if (r1g < N) {
                    __half2 h = __floats2half2_rn(c2[mf][nf][2] * dv1, c2[mf][nf][3] * dv1);
                    *(__half2*)(y2 + (size_t)r1g * COUT + cb) = h;
                }
            }
        }
    }
}

// ================================ launch ===================================
extern "C" void kernel_launch(void* const* d_in, const int* in_sizes, int n_in,
                              void* d_out, int out_size) {
    const float* x     = (const float*)d_in[0];
    const void*  edges = d_in[1];
    const float* W1    = (const float*)d_in[2];
    const float* b1    = (const float*)d_in[3];
    const float* W2    = (const float*)d_in[4];
    const float* b2    = (const float*)d_in[5];
    float* out = (float*)d_out;

    const int N = in_sizes[0] / F_IN;
    const int E = in_sizes[1] / 2;
    const int nchunks = (N + SCAN_CHUNK - 1) / SCAN_CHUNK;

    int *deg, *cursor, *offsets, *partials, *ssrc;
    __half *y1, *y2;
    float *aggx, *dinv;
    cudaGetSymbolAddress((void**)&deg,      g_deg);
    cudaGetSymbolAddress((void**)&cursor,   g_cursor);
    cudaGetSymbolAddress((void**)&offsets,  g_offsets);
    cudaGetSymbolAddress((void**)&partials, g_partials);
    cudaGetSymbolAddress((void**)&ssrc,     g_sorted_src);
    cudaGetSymbolAddress((void**)&dinv,     g_dinv);
    cudaGetSymbolAddress((void**)&y1,       g_y1);
    cudaGetSymbolAddress((void**)&aggx,     g_aggx);
    cudaGetSymbolAddress((void**)&y2,       g_y2);

    cudaFuncSetAttribute(k_gemm, cudaFuncAttributeMaxDynamicSharedMemorySize, GEMM_SMEM);

    // lazy one-time resource creation (no device memory; same work every call)
    static cudaStream_t s_side = nullptr;
    static cudaEvent_t  ev_fork = nullptr, ev_join = nullptr;
    if (s_side == nullptr) {
        cudaStreamCreateWithFlags(&s_side, cudaStreamNonBlocking);
        cudaEventCreateWithFlags(&ev_fork, cudaEventDisableTiming);
        cudaEventCreateWithFlags(&ev_join, cudaEventDisableTiming);
    }

    k_hist<<<(E + 255) / 256, 256>>>(edges, deg, E);
    k_scan_a<<<nchunks, 256>>>(deg, partials, N);
    k_scan_c<<<nchunks, 256>>>(deg, partials, offsets, cursor, dinv, nchunks, N);

    // fork: y1 (DRAM-bound) on side stream, concurrent with place (atomic-bound)
    cudaEventRecord(ev_fork, 0);
    cudaStreamWaitEvent(s_side, ev_fork, 0);
    k_y1<<<(N * 16 + 255) / 256, 256, 0, s_side>>>(x, dinv, y1, N);
    cudaEventRecord(ev_join, s_side);

    k_place<<<(E + 255) / 256, 256>>>(edges, cursor, ssrc, E);

    // join
    cudaStreamWaitEvent(0, ev_join, 0);

    k_agg1<<<(N * 8 + 255) / 256, 256>>>(ssrc, offsets, dinv, y1, aggx, N);
    k_gemm<<<(N + 127) / 128, 256, GEMM_SMEM>>>(aggx, W1, b1, W2, dinv, y2, N);
    k_agg2<<<(N * 5 + 255) / 256, 256>>>(ssrc, offsets, dinv, y2, b2, out, N);
}